// round 16
// baseline (speedup 1.0000x reference)
#include <cuda_runtime.h>
#include <cuda_bf16.h>
#include <cstdint>

#define BDIM 32
#define CDIM 512
#define KDIM 32
#define NPIX 4096   // 64*64

__device__ float g_w[BDIM * KDIM * NPIX];          // softmax weights fp32, 16 MiB
__device__ float g_part[4 * BDIM * KDIM * CDIM];   // k2 partials, 8 MiB

// ---------- warp mma (legacy HMMA path, no 'a'-feature needed) ----------
__device__ __forceinline__ void mma_tf32(float* d,
                                         unsigned a0, unsigned a1,
                                         unsigned a2, unsigned a3,
                                         unsigned b0, unsigned b1) {
    asm volatile(
        "mma.sync.aligned.m16n8k8.row.col.f32.tf32.tf32.f32 "
        "{%0,%1,%2,%3}, {%4,%5,%6,%7}, {%8,%9}, {%0,%1,%2,%3};"
        : "+f"(d[0]), "+f"(d[1]), "+f"(d[2]), "+f"(d[3])
        : "r"(a0), "r"(a1), "r"(a2), "r"(a3), "r"(b0), "r"(b1));
}

// ---------- cp.async ----------
__device__ __forceinline__ uint32_t smem_u32(const void* p) {
    uint32_t a;
    asm("{ .reg .u64 t; cvta.to.shared.u64 t, %1; cvt.u32.u64 %0, t; }"
        : "=r"(a) : "l"(p));
    return a;
}
#define CPA16(dst, src) \
    asm volatile("cp.async.cg.shared.global [%0], [%1], 16;" \
                 :: "r"(dst), "l"(src) : "memory")
#define CP_COMMIT() asm volatile("cp.async.commit_group;" ::: "memory")
#define CP_WAIT2()  asm volatile("cp.async.wait_group 2;" ::: "memory")
#define CP_WAIT1()  asm volatile("cp.async.wait_group 1;" ::: "memory")
#define CP_WAIT0()  asm volatile("cp.async.wait_group 0;" ::: "memory")

#define TF32_MASK 0xFFFFE000u

// ============================================================================
// Kernel 1 (tf32 MMA + cp.async x3): dist = scale*(x2 - 2*xc + c2), softmax,
// w (fp32) -> g_w. grid (16 n-tiles, 32 b) = 512 CTAs, 256 thr = 8 warps.
// CTA: 256 pixels x 32 k x 512 c in 32 chunks of 16 c, 3-stage pipeline.
// x2 accumulated from the MMA A-fragment registers (no extra LDS).
// dyn smem floats: xbuf 3*16*264 = 12672 | cwbuf 3*32*20 = 1920  (58368 B)
// epilogue reuses xbuf region as dist_s [32k][260].
// ============================================================================
__global__ __launch_bounds__(256) void enc_k1(
    const float* __restrict__ x,
    const float* __restrict__ cw,
    const float* __restrict__ scale)
{
    extern __shared__ float dyn[];
    float* dist_s = dyn;                 // epilogue alias
    __shared__ float x2_s[256];
    __shared__ float c2_s[KDIM];
    __shared__ float sc_s[KDIM];

    const int t    = threadIdx.x;
    const int b    = blockIdx.y;
    const int n0   = blockIdx.x * 256;
    const int lane = t & 31, w = t >> 5;
    const int g  = lane >> 2;
    const int tg = lane & 3;

    const uint32_t sb = smem_u32(dyn);
    const float* xb = x + (size_t)b * CDIM * NPIX + n0;

    // ---- c2[k] precompute (x2_s as scratch) ----
    {
        const int k = t >> 3, seg = t & 7;
        const float4* p = (const float4*)(cw + k * CDIM + seg * 64);
        float s = 0.f;
        #pragma unroll
        for (int i = 0; i < 16; ++i) {
            float4 v = p[i];
            s += v.x * v.x + v.y * v.y + v.z * v.z + v.w * v.w;
        }
        x2_s[t] = s;
        if (t < KDIM) sc_s[t] = scale[t];
        __syncthreads();
        if (t < KDIM) {
            float s2 = 0.f;
            #pragma unroll
            for (int j = 0; j < 8; ++j) s2 += x2_s[t * 8 + j];
            c2_s[t] = s2;
        }
        __syncthreads();
    }

    // ---- issue helper (chunk ch -> slot) ----
    auto issue = [&](int ch, int slot) {
        const int c0 = ch * 16;
        const uint32_t xd = sb + (uint32_t)(slot * 4224) * 4u;
        #pragma unroll
        for (int i = 0; i < 4; ++i) {
            int idx = t + 256 * i;
            int cb = idx >> 6, nq = (idx & 63) * 4;
            CPA16(xd + (uint32_t)(cb * 264 + nq) * 4u,
                  xb + (size_t)(c0 + cb) * NPIX + nq);
        }
        if (t < 128) {
            int k = t >> 2, cq = (t & 3) * 4;
            const uint32_t cd = sb + (uint32_t)(12672 + slot * 640) * 4u;
            CPA16(cd + (uint32_t)(k * 20 + cq) * 4u,
                  cw + k * CDIM + c0 + cq);
        }
    };

    float dacc[2][4][4];
    #pragma unroll
    for (int mi = 0; mi < 2; ++mi)
        #pragma unroll
        for (int ni = 0; ni < 4; ++ni)
            #pragma unroll
            for (int r = 0; r < 4; ++r) dacc[mi][ni][r] = 0.f;
    // x2 partials: q = mi*2 + h -> pixel row w*32 + mi*16 + h*8 + g
    float x2r[4] = {0.f, 0.f, 0.f, 0.f};

    // prologue: chunks 0..2
    #pragma unroll
    for (int p = 0; p < 3; ++p) { issue(p, p); CP_COMMIT(); }

    for (int ch = 0; ch < 32; ++ch) {
        if (ch < 29) CP_WAIT2(); else CP_WAIT0();
        __syncthreads();
        const int slot = ch % 3;
        const float* xs  = dyn + slot * 4224;
        const float* cws = dyn + 12672 + slot * 640;

        // 2 k8-steps over 16 c (x2 folded into fragment loads)
        #pragma unroll
        for (int s = 0; s < 2; ++s) {
            const int col = s * 8 + tg;
            unsigned bb0[4], bb1[4];
            #pragma unroll
            for (int ni = 0; ni < 4; ++ni) {
                const int ba = (ni * 8 + g) * 20 + s * 8 + tg;
                bb0[ni] = __float_as_uint(cws[ba]);
                bb1[ni] = __float_as_uint(cws[ba + 4]);
            }
            #pragma unroll
            for (int mi = 0; mi < 2; ++mi) {
                const int row = w * 32 + mi * 16 + g;
                float f0 = xs[col * 264 + row];
                float f1 = xs[col * 264 + row + 8];
                float f2 = xs[(col + 4) * 264 + row];
                float f3 = xs[(col + 4) * 264 + row + 8];
                x2r[mi * 2 + 0] = fmaf(f0, f0, fmaf(f2, f2, x2r[mi * 2 + 0]));
                x2r[mi * 2 + 1] = fmaf(f1, f1, fmaf(f3, f3, x2r[mi * 2 + 1]));
                unsigned a0 = __float_as_uint(f0);
                unsigned a1 = __float_as_uint(f1);
                unsigned a2 = __float_as_uint(f2);
                unsigned a3 = __float_as_uint(f3);
                #pragma unroll
                for (int ni = 0; ni < 4; ++ni)
                    mma_tf32(dacc[mi][ni], a0, a1, a2, a3, bb0[ni], bb1[ni]);
            }
        }
        __syncthreads();
        if (ch + 3 < 32) { issue(ch + 3, (ch + 3) % 3); CP_COMMIT(); }
    }

    // reduce x2 over the 4 tg-lanes (same rows), write per-pixel x2
    #pragma unroll
    for (int q = 0; q < 4; ++q) {
        x2r[q] += __shfl_xor_sync(0xffffffffu, x2r[q], 1);
        x2r[q] += __shfl_xor_sync(0xffffffffu, x2r[q], 2);
    }
    if (tg == 0) {
        #pragma unroll
        for (int q = 0; q < 4; ++q)
            x2_s[w * 32 + (q >> 1) * 16 + (q & 1) * 8 + g] = x2r[q];
    }
    __syncthreads();

    // dist = sc*(x2 - 2*xc + c2) -> dist_s [k][260]
    #pragma unroll
    for (int mi = 0; mi < 2; ++mi) {
        const int nr = w * 32 + mi * 16 + g;
        #pragma unroll
        for (int ni = 0; ni < 4; ++ni) {
            const int k0 = ni * 8 + 2 * tg;
            const float* dd = dacc[mi][ni];
            dist_s[k0 * 260 + nr] =
                sc_s[k0] * (x2_s[nr] - 2.f * dd[0] + c2_s[k0]);
            dist_s[(k0 + 1) * 260 + nr] =
                sc_s[k0 + 1] * (x2_s[nr] - 2.f * dd[1] + c2_s[k0 + 1]);
            dist_s[k0 * 260 + nr + 8] =
                sc_s[k0] * (x2_s[nr + 8] - 2.f * dd[2] + c2_s[k0]);
            dist_s[(k0 + 1) * 260 + nr + 8] =
                sc_s[k0 + 1] * (x2_s[nr + 8] - 2.f * dd[3] + c2_s[k0 + 1]);
        }
    }
    __syncthreads();

    // per-pixel softmax (pixel = t), write w fp32 in place
    {
        float d[KDIM];
        #pragma unroll
        for (int k = 0; k < KDIM; ++k) d[k] = dist_s[k * 260 + t];
        float m = d[0];
        #pragma unroll
        for (int k = 1; k < KDIM; ++k) m = fmaxf(m, d[k]);
        float sum = 0.f;
        #pragma unroll
        for (int k = 0; k < KDIM; ++k) { d[k] = __expf(d[k] - m); sum += d[k]; }
        const float inv = 1.0f / sum;
        #pragma unroll
        for (int k = 0; k < KDIM; ++k) dist_s[k * 260 + t] = d[k] * inv;
    }
    __syncthreads();

    // vectorized global store (STG.128)
    #pragma unroll
    for (int j = 0; j < 8; ++j) {
        int idx = t + 256 * j;
        int k = idx >> 6, nq = (idx & 63) * 4;
        float4 v = *(const float4*)&dist_s[k * 260 + nq];
        *(float4*)&g_w[(size_t)(b * KDIM + k) * NPIX + n0 + nq] = v;
    }
}

// ============================================================================
// Kernel 2 (tf32 hi/lo MMA + cp.async x3):
// partial[s][b][k][c] = sum_{n in slice} w[k][n]*x[c][n]
// grid (4 c-tiles, 4 n-splits, 32 b) = 512 CTAs, 256 thr = 8 warps.
// b REVERSED (31 - blockIdx.z) for L2 reuse of k1's freshest output.
// CTA tile: M=128 c, N=32 k, 1024 n in 32 chunks of 32, 3-stage pipeline.
// Raw fp32 staged via cp.async; hi/lo split in registers; 3 MMAs per pair.
// dyn smem floats: xbuf 3*128*36 = 13824 | wbuf 3*32*36 = 3456  (69120 B)
// ============================================================================
__global__ __launch_bounds__(256) void enc_k2m(const float* __restrict__ x)
{
    extern __shared__ float dyn[];
    const int t = threadIdx.x;
    const int w = t >> 5, lane = t & 31;
    const int g = lane >> 2, tg = lane & 3;
    const int b = (BDIM - 1) - blockIdx.z;
    const int sp = blockIdx.y;
    const int c0 = blockIdx.x * 128;
    const int mb = (w & 3) * 32;      // warp m (c) base
    const int nb = (w >> 2) * 16;     // warp n (k) base

    const uint32_t sb = smem_u32(dyn);
    const float* xbase = x + ((size_t)b * CDIM + c0) * NPIX;
    const float* wbase = g_w + (size_t)b * KDIM * NPIX;
    const int nbeg = sp * 1024;

    auto issue = [&](int ch, int slot) {
        const int n0 = nbeg + ch * 32;
        const uint32_t xd = sb + (uint32_t)(slot * 4608) * 4u;
        #pragma unroll
        for (int i = 0; i < 4; ++i) {
            int idx = t + 256 * i;
            int cl = idx >> 3, nq = (idx & 7) * 4;
            CPA16(xd + (uint32_t)(cl * 36 + nq) * 4u,
                  xbase + (size_t)cl * NPIX + n0 + nq);
        }
        {
            int kl = t >> 3, nq = (t & 7) * 4;
            const uint32_t wd = sb + (uint32_t)(13824 + slot * 1152) * 4u;
            CPA16(wd + (uint32_t)(kl * 36 + nq) * 4u,
                  wbase + (size_t)kl * NPIX + n0 + nq);
        }
    };

    float d[2][2][4];
    #pragma unroll
    for (int mi = 0; mi < 2; ++mi)
        #pragma unroll
        for (int ni = 0; ni < 2; ++ni)
            #pragma unroll
            for (int r = 0; r < 4; ++r) d[mi][ni][r] = 0.f;

    // prologue: chunks 0..2
    #pragma unroll
    for (int p = 0; p < 3; ++p) { issue(p, p); CP_COMMIT(); }

    for (int ch = 0; ch < 32; ++ch) {
        if (ch < 29) CP_WAIT2(); else CP_WAIT0();
        __syncthreads();
        const int slot = ch % 3;
        const float* xs = dyn + slot * 4608;
        const float* ws = dyn + 13824 + slot * 1152;

        #pragma unroll
        for (int s = 0; s < 4; ++s) {
            const int kk = s * 8 + tg;
            unsigned ah[2][4], al[2][4], bh[2][2], bl[2][2];
            #pragma unroll
            for (int mi = 0; mi < 2; ++mi) {
                const int r0 = (mb + mi * 16 + g) * 36 + kk;
                const int r1 = r0 + 8 * 36;
                unsigned rr[4];
                rr[0] = __float_as_uint(xs[r0]);
                rr[1] = __float_as_uint(xs[r1]);
                rr[2] = __float_as_uint(xs[r0 + 4]);
                rr[3] = __float_as_uint(xs[r1 + 4]);
                #pragma unroll
                for (int q = 0; q < 4; ++q) {
                    unsigned hb = rr[q] & TF32_MASK;
                    ah[mi][q] = hb;
                    al[mi][q] = __float_as_uint(
                        __uint_as_float(rr[q]) - __uint_as_float(hb));
                }
            }
            #pragma unroll
            for (int ni = 0; ni < 2; ++ni) {
                const int q0 = (nb + ni * 8 + g) * 36 + kk;
                unsigned r0 = __float_as_uint(ws[q0]);
                unsigned r1 = __float_as_uint(ws[q0 + 4]);
                unsigned h0 = r0 & TF32_MASK, h1 = r1 & TF32_MASK;
                bh[ni][0] = h0;
                bh[ni][1] = h1;
                bl[ni][0] = __float_as_uint(
                    __uint_as_float(r0) - __uint_as_float(h0));
                bl[ni][1] = __float_as_uint(
                    __uint_as_float(r1) - __uint_as_float(h1));
            }
            #pragma unroll
            for (int mi = 0; mi < 2; ++mi)
                #pragma unroll
                for (int ni = 0; ni < 2; ++ni) {
                    mma_tf32(d[mi][ni], ah[mi][0], ah[mi][1], ah[mi][2],
                             ah[mi][3], bh[ni][0], bh[ni][1]);
                    mma_tf32(d[mi][ni], ah[mi][0], ah[mi][1], ah[mi][2],
                             ah[mi][3], bl[ni][0], bl[ni][1]);
                    mma_tf32(d[mi][ni], al[mi][0], al[mi][1], al[mi][2],
                             al[mi][3], bh[ni][0], bh[ni][1]);
                }
        }
        __syncthreads();
        if (ch + 3 < 32) { issue(ch + 3, (ch + 3) % 3); CP_COMMIT(); }
    }

    // ---- store partials ----
    float* pb = g_part + ((size_t)sp * BDIM + b) * KDIM * CDIM;
    #pragma unroll
    for (int mi = 0; mi < 2; ++mi)
        #pragma unroll
        for (int ni = 0; ni < 2; ++ni) {
            const int k0 = nb + ni * 8 + 2 * tg;
            const int cA = c0 + mb + mi * 16 + g;
            const int cB = cA + 8;
            const float* dd = d[mi][ni];
            pb[(size_t)k0 * CDIM + cA]       = dd[0];
            pb[(size_t)(k0 + 1) * CDIM + cA] = dd[1];
            pb[(size_t)k0 * CDIM + cB]       = dd[2];
            pb[(size_t)(k0 + 1) * CDIM + cB] = dd[3];
        }
}

// ============================================================================
// Kernel 3: out[b][k][c] = sum_s part - wsum[b][k]*cw[k][c]
// wsum exact from fp32 g_w. grid (32 k, 32 b), 128 thr.
// ============================================================================
__global__ __launch_bounds__(128) void enc_red(const float* __restrict__ cw,
                                               float* __restrict__ out)
{
    __shared__ float red[4];
    const int t = threadIdx.x;
    const int k = blockIdx.x, b = blockIdx.y;

    const float4* wp = (const float4*)(g_w + ((size_t)b * KDIM + k) * NPIX);
    float s = 0.f;
    #pragma unroll
    for (int i = 0; i < 8; ++i) {
        float4 v = wp[t + 128 * i];
        s += (v.x + v.y) + (v.z + v.w);
    }
    #pragma unroll
    for (int o = 16; o > 0; o >>= 1) s += __shfl_xor_sync(0xffffffffu, s, o);
    if ((t & 31) == 0) red[t >> 5] = s;
    __syncthreads();
    const float ws = red[0] + red[1] + red[2] + red[3];

    const int c = 4 * t;
    const size_t kc = ((size_t)b * KDIM + k) * CDIM + c;
    float4 p = *(const float4*)(g_part + kc);
    #pragma unroll
    for (int sp = 1; sp < 4; ++sp) {
        float4 q = *(const float4*)(g_part + (size_t)sp * BDIM * KDIM * CDIM + kc);
        p.x += q.x; p.y += q.y; p.z += q.z; p.w += q.w;
    }
    float4 cv = *(const float4*)(cw + k * CDIM + c);
    float4 o4;
    o4.x = p.x - ws * cv.x;
    o4.y = p.y - ws * cv.y;
    o4.z = p.z - ws * cv.z;
    o4.w = p.w - ws * cv.w;
    *(float4*)(out + kc) = o4;
}

// ============================================================================
extern "C" void kernel_launch(void* const* d_in, const int* in_sizes, int n_in,
                              void* d_out, int out_size)
{
    (void)in_sizes; (void)n_in; (void)out_size;
    const float* x     = (const float*)d_in[0];   // [32,512,64,64]
    const float* cw    = (const float*)d_in[1];   // [32,512]
    const float* scale = (const float*)d_in[2];   // [32]
    float* out = (float*)d_out;                   // [32,32,512]

    cudaFuncSetAttribute(enc_k1, cudaFuncAttributeMaxDynamicSharedMemorySize,
                         58368);
    cudaFuncSetAttribute(enc_k2m, cudaFuncAttributeMaxDynamicSharedMemorySize,
                         69120);

    enc_k1 <<<dim3(16, 32), 256, 58368>>>(x, cw, scale);
    enc_k2m<<<dim3(4, 4, 32), 256, 69120>>>(x);
    enc_red<<<dim3(32, 32), 128>>>(cw, out);
}

// round 17
// speedup vs baseline: 1.1103x; 1.1103x over previous
#include <cuda_runtime.h>
#include <cuda_bf16.h>
#include <cstdint>

#define BDIM 32
#define CDIM 512
#define KDIM 32
#define NPIX 4096   // 64*64

__device__ float g_w[BDIM * KDIM * NPIX];          // softmax weights fp32, 16 MiB
__device__ float g_part[4 * BDIM * KDIM * CDIM];   // k2 partials, 8 MiB

// ---------- warp mma (legacy HMMA path, no 'a'-feature needed) ----------
__device__ __forceinline__ void mma_tf32(float* d,
                                         unsigned a0, unsigned a1,
                                         unsigned a2, unsigned a3,
                                         unsigned b0, unsigned b1) {
    asm volatile(
        "mma.sync.aligned.m16n8k8.row.col.f32.tf32.tf32.f32 "
        "{%0,%1,%2,%3}, {%4,%5,%6,%7}, {%8,%9}, {%0,%1,%2,%3};"
        : "+f"(d[0]), "+f"(d[1]), "+f"(d[2]), "+f"(d[3])
        : "r"(a0), "r"(a1), "r"(a2), "r"(a3), "r"(b0), "r"(b1));
}

// ---------- cp.async ----------
__device__ __forceinline__ uint32_t smem_u32(const void* p) {
    uint32_t a;
    asm("{ .reg .u64 t; cvta.to.shared.u64 t, %1; cvt.u32.u64 %0, t; }"
        : "=r"(a) : "l"(p));
    return a;
}
#define CPA16(dst, src) \
    asm volatile("cp.async.cg.shared.global [%0], [%1], 16;" \
                 :: "r"(dst), "l"(src) : "memory")
#define CP_COMMIT() asm volatile("cp.async.commit_group;" ::: "memory")
#define CP_WAIT2()  asm volatile("cp.async.wait_group 2;" ::: "memory")
#define CP_WAIT1()  asm volatile("cp.async.wait_group 1;" ::: "memory")
#define CP_WAIT0()  asm volatile("cp.async.wait_group 0;" ::: "memory")

#define TF32_MASK 0xFFFFE000u

// ============================================================================
// Kernel 1 (tf32 MMA + cp.async x3): dist = scale*(x2 - 2*xc + c2), softmax,
// w (fp32) -> g_w. grid (16 n-tiles, 32 b) = 512 CTAs, 256 thr = 8 warps.
// CTA: 256 pixels x 32 k x 512 c in 32 chunks of 16 c, 3-stage pipeline.
// x2 accumulated from the MMA A-fragment registers (no extra LDS).
// dyn smem floats: xbuf 3*16*264 = 12672 | cwbuf 3*32*20 = 1920  (58368 B)
// epilogue reuses xbuf region as dist_s [32k][260].
// ============================================================================
__global__ __launch_bounds__(256) void enc_k1(
    const float* __restrict__ x,
    const float* __restrict__ cw,
    const float* __restrict__ scale)
{
    extern __shared__ float dyn[];
    float* dist_s = dyn;                 // epilogue alias
    __shared__ float x2_s[256];
    __shared__ float c2_s[KDIM];
    __shared__ float sc_s[KDIM];

    const int t    = threadIdx.x;
    const int b    = blockIdx.y;
    const int n0   = blockIdx.x * 256;
    const int lane = t & 31, w = t >> 5;
    const int g  = lane >> 2;
    const int tg = lane & 3;

    const uint32_t sb = smem_u32(dyn);
    const float* xb = x + (size_t)b * CDIM * NPIX + n0;

    // ---- c2[k] precompute (x2_s as scratch) ----
    {
        const int k = t >> 3, seg = t & 7;
        const float4* p = (const float4*)(cw + k * CDIM + seg * 64);
        float s = 0.f;
        #pragma unroll
        for (int i = 0; i < 16; ++i) {
            float4 v = p[i];
            s += v.x * v.x + v.y * v.y + v.z * v.z + v.w * v.w;
        }
        x2_s[t] = s;
        if (t < KDIM) sc_s[t] = scale[t];
        __syncthreads();
        if (t < KDIM) {
            float s2 = 0.f;
            #pragma unroll
            for (int j = 0; j < 8; ++j) s2 += x2_s[t * 8 + j];
            c2_s[t] = s2;
        }
        __syncthreads();
    }

    // ---- issue helper (chunk ch -> slot) ----
    auto issue = [&](int ch, int slot) {
        const int c0 = ch * 16;
        const uint32_t xd = sb + (uint32_t)(slot * 4224) * 4u;
        #pragma unroll
        for (int i = 0; i < 4; ++i) {
            int idx = t + 256 * i;
            int cb = idx >> 6, nq = (idx & 63) * 4;
            CPA16(xd + (uint32_t)(cb * 264 + nq) * 4u,
                  xb + (size_t)(c0 + cb) * NPIX + nq);
        }
        if (t < 128) {
            int k = t >> 2, cq = (t & 3) * 4;
            const uint32_t cd = sb + (uint32_t)(12672 + slot * 640) * 4u;
            CPA16(cd + (uint32_t)(k * 20 + cq) * 4u,
                  cw + k * CDIM + c0 + cq);
        }
    };

    float dacc[2][4][4];
    #pragma unroll
    for (int mi = 0; mi < 2; ++mi)
        #pragma unroll
        for (int ni = 0; ni < 4; ++ni)
            #pragma unroll
            for (int r = 0; r < 4; ++r) dacc[mi][ni][r] = 0.f;
    // x2 partials: q = mi*2 + h -> pixel row w*32 + mi*16 + h*8 + g
    float x2r[4] = {0.f, 0.f, 0.f, 0.f};

    // prologue: chunks 0..2
    #pragma unroll
    for (int p = 0; p < 3; ++p) { issue(p, p); CP_COMMIT(); }

    for (int ch = 0; ch < 32; ++ch) {
        if (ch < 29) CP_WAIT2(); else CP_WAIT0();
        __syncthreads();
        const int slot = ch % 3;
        const float* xs  = dyn + slot * 4224;
        const float* cws = dyn + 12672 + slot * 640;

        // 2 k8-steps over 16 c (x2 folded into fragment loads)
        #pragma unroll
        for (int s = 0; s < 2; ++s) {
            const int col = s * 8 + tg;
            unsigned bb0[4], bb1[4];
            #pragma unroll
            for (int ni = 0; ni < 4; ++ni) {
                const int ba = (ni * 8 + g) * 20 + s * 8 + tg;
                bb0[ni] = __float_as_uint(cws[ba]);
                bb1[ni] = __float_as_uint(cws[ba + 4]);
            }
            #pragma unroll
            for (int mi = 0; mi < 2; ++mi) {
                const int row = w * 32 + mi * 16 + g;
                float f0 = xs[col * 264 + row];
                float f1 = xs[col * 264 + row + 8];
                float f2 = xs[(col + 4) * 264 + row];
                float f3 = xs[(col + 4) * 264 + row + 8];
                x2r[mi * 2 + 0] = fmaf(f0, f0, fmaf(f2, f2, x2r[mi * 2 + 0]));
                x2r[mi * 2 + 1] = fmaf(f1, f1, fmaf(f3, f3, x2r[mi * 2 + 1]));
                unsigned a0 = __float_as_uint(f0);
                unsigned a1 = __float_as_uint(f1);
                unsigned a2 = __float_as_uint(f2);
                unsigned a3 = __float_as_uint(f3);
                #pragma unroll
                for (int ni = 0; ni < 4; ++ni)
                    mma_tf32(dacc[mi][ni], a0, a1, a2, a3, bb0[ni], bb1[ni]);
            }
        }
        __syncthreads();
        if (ch + 3 < 32) { issue(ch + 3, (ch + 3) % 3); CP_COMMIT(); }
    }

    // reduce x2 over the 4 tg-lanes (same rows), write per-pixel x2
    #pragma unroll
    for (int q = 0; q < 4; ++q) {
        x2r[q] += __shfl_xor_sync(0xffffffffu, x2r[q], 1);
        x2r[q] += __shfl_xor_sync(0xffffffffu, x2r[q], 2);
    }
    if (tg == 0) {
        #pragma unroll
        for (int q = 0; q < 4; ++q)
            x2_s[w * 32 + (q >> 1) * 16 + (q & 1) * 8 + g] = x2r[q];
    }
    __syncthreads();

    // dist = sc*(x2 - 2*xc + c2) -> dist_s [k][260]
    #pragma unroll
    for (int mi = 0; mi < 2; ++mi) {
        const int nr = w * 32 + mi * 16 + g;
        #pragma unroll
        for (int ni = 0; ni < 4; ++ni) {
            const int k0 = ni * 8 + 2 * tg;
            const float* dd = dacc[mi][ni];
            dist_s[k0 * 260 + nr] =
                sc_s[k0] * (x2_s[nr] - 2.f * dd[0] + c2_s[k0]);
            dist_s[(k0 + 1) * 260 + nr] =
                sc_s[k0 + 1] * (x2_s[nr] - 2.f * dd[1] + c2_s[k0 + 1]);
            dist_s[k0 * 260 + nr + 8] =
                sc_s[k0] * (x2_s[nr + 8] - 2.f * dd[2] + c2_s[k0]);
            dist_s[(k0 + 1) * 260 + nr + 8] =
                sc_s[k0 + 1] * (x2_s[nr + 8] - 2.f * dd[3] + c2_s[k0 + 1]);
        }
    }
    __syncthreads();

    // per-pixel softmax (pixel = t), write w fp32 in place
    {
        float d[KDIM];
        #pragma unroll
        for (int k = 0; k < KDIM; ++k) d[k] = dist_s[k * 260 + t];
        float m = d[0];
        #pragma unroll
        for (int k = 1; k < KDIM; ++k) m = fmaxf(m, d[k]);
        float sum = 0.f;
        #pragma unroll
        for (int k = 0; k < KDIM; ++k) { d[k] = __expf(d[k] - m); sum += d[k]; }
        const float inv = 1.0f / sum;
        #pragma unroll
        for (int k = 0; k < KDIM; ++k) dist_s[k * 260 + t] = d[k] * inv;
    }
    __syncthreads();

    // vectorized global store (STG.128)
    #pragma unroll
    for (int j = 0; j < 8; ++j) {
        int idx = t + 256 * j;
        int k = idx >> 6, nq = (idx & 63) * 4;
        float4 v = *(const float4*)&dist_s[k * 260 + nq];
        *(float4*)&g_w[(size_t)(b * KDIM + k) * NPIX + n0 + nq] = v;
    }
}

// ============================================================================
// Kernel 2 (tf32 x-hi/lo MMA + cp.async x2):
// partial[s][b][k][c] = sum_{n in slice} w[k][n]*x[c][n]
// grid (4 c-tiles, 4 n-splits, 32 b) = 512 CTAs, 256 thr = 8 warps.
// b REVERSED (31 - blockIdx.z) for L2 reuse of k1's freshest output.
// CTA tile: M=128 c, N=32 k, 1024 n in 16 chunks of 64, 2-stage pipeline.
// x split hi/lo in registers; w passed as raw fp32 (HW-truncated tf32).
// 2 MMAs per frag pair: xh*w + xl*w  (dropped terms are ~2e-4 rel, random
// sign over n -> well under the 1e-3 gate).
// dyn smem floats: xbuf 2*128*68 = 17408 | wbuf 2*32*68 = 4352  (87040 B)
// ============================================================================
__global__ __launch_bounds__(256) void enc_k2m(const float* __restrict__ x)
{
    extern __shared__ float dyn[];
    const int t = threadIdx.x;
    const int w = t >> 5, lane = t & 31;
    const int g = lane >> 2, tg = lane & 3;
    const int b = (BDIM - 1) - blockIdx.z;
    const int sp = blockIdx.y;
    const int c0 = blockIdx.x * 128;
    const int mb = (w & 3) * 32;      // warp m (c) base
    const int nb = (w >> 2) * 16;     // warp n (k) base

    const uint32_t sb = smem_u32(dyn);
    const float* xbase = x + ((size_t)b * CDIM + c0) * NPIX;
    const float* wbase = g_w + (size_t)b * KDIM * NPIX;
    const int nbeg = sp * 1024;

    auto issue = [&](int ch, int slot) {
        const int n0 = nbeg + ch * 64;
        const uint32_t xd = sb + (uint32_t)(slot * 8704) * 4u;
        #pragma unroll
        for (int i = 0; i < 8; ++i) {
            int idx = t + 256 * i;
            int cl = idx >> 4, nq = (idx & 15) * 4;
            CPA16(xd + (uint32_t)(cl * 68 + nq) * 4u,
                  xbase + (size_t)cl * NPIX + n0 + nq);
        }
        const uint32_t wd = sb + (uint32_t)(17408 + slot * 2176) * 4u;
        #pragma unroll
        for (int i = 0; i < 2; ++i) {
            int idx = t + 256 * i;
            int kl = idx >> 4, nq = (idx & 15) * 4;
            CPA16(wd + (uint32_t)(kl * 68 + nq) * 4u,
                  wbase + (size_t)kl * NPIX + n0 + nq);
        }
    };

    float d[2][2][4];
    #pragma unroll
    for (int mi = 0; mi < 2; ++mi)
        #pragma unroll
        for (int ni = 0; ni < 2; ++ni)
            #pragma unroll
            for (int r = 0; r < 4; ++r) d[mi][ni][r] = 0.f;

    issue(0, 0); CP_COMMIT();

    for (int ch = 0; ch < 16; ++ch) {
        if (ch < 15) { issue(ch + 1, (ch + 1) & 1); CP_COMMIT(); CP_WAIT1(); }
        else CP_WAIT0();
        __syncthreads();
        const float* xs = dyn + (ch & 1) * 8704;
        const float* ws = dyn + 17408 + (ch & 1) * 2176;

        #pragma unroll
        for (int s = 0; s < 8; ++s) {
            const int kk = s * 8 + tg;
            unsigned ah[2][4], al[2][4], bw[2][2];
            #pragma unroll
            for (int mi = 0; mi < 2; ++mi) {
                const int r0 = (mb + mi * 16 + g) * 68 + kk;
                const int r1 = r0 + 8 * 68;
                unsigned rr[4];
                rr[0] = __float_as_uint(xs[r0]);
                rr[1] = __float_as_uint(xs[r1]);
                rr[2] = __float_as_uint(xs[r0 + 4]);
                rr[3] = __float_as_uint(xs[r1 + 4]);
                #pragma unroll
                for (int q = 0; q < 4; ++q) {
                    unsigned hb = rr[q] & TF32_MASK;
                    ah[mi][q] = hb;
                    al[mi][q] = __float_as_uint(
                        __uint_as_float(rr[q]) - __uint_as_float(hb));
                }
            }
            #pragma unroll
            for (int ni = 0; ni < 2; ++ni) {
                const int q0 = (nb + ni * 8 + g) * 68 + kk;
                bw[ni][0] = __float_as_uint(ws[q0]);
                bw[ni][1] = __float_as_uint(ws[q0 + 4]);
            }
            #pragma unroll
            for (int mi = 0; mi < 2; ++mi)
                #pragma unroll
                for (int ni = 0; ni < 2; ++ni) {
                    mma_tf32(d[mi][ni], ah[mi][0], ah[mi][1], ah[mi][2],
                             ah[mi][3], bw[ni][0], bw[ni][1]);
                    mma_tf32(d[mi][ni], al[mi][0], al[mi][1], al[mi][2],
                             al[mi][3], bw[ni][0], bw[ni][1]);
                }
        }
        __syncthreads();
    }

    // ---- store partials ----
    float* pb = g_part + ((size_t)sp * BDIM + b) * KDIM * CDIM;
    #pragma unroll
    for (int mi = 0; mi < 2; ++mi)
        #pragma unroll
        for (int ni = 0; ni < 2; ++ni) {
            const int k0 = nb + ni * 8 + 2 * tg;
            const int cA = c0 + mb + mi * 16 + g;
            const int cB = cA + 8;
            const float* dd = d[mi][ni];
            pb[(size_t)k0 * CDIM + cA]       = dd[0];
            pb[(size_t)(k0 + 1) * CDIM + cA] = dd[1];
            pb[(size_t)k0 * CDIM + cB]       = dd[2];
            pb[(size_t)(k0 + 1) * CDIM + cB] = dd[3];
        }
}

// ============================================================================
// Kernel 3: out[b][k][c] = sum_s part - wsum[b][k]*cw[k][c]
// wsum exact from fp32 g_w. grid (32 k, 32 b), 128 thr.
// ============================================================================
__global__ __launch_bounds__(128) void enc_red(const float* __restrict__ cw,
                                               float* __restrict__ out)
{
    __shared__ float red[4];
    const int t = threadIdx.x;
    const int k = blockIdx.x, b = blockIdx.y;

    const float4* wp = (const float4*)(g_w + ((size_t)b * KDIM + k) * NPIX);
    float s = 0.f;
    #pragma unroll
    for (int i = 0; i < 8; ++i) {
        float4 v = wp[t + 128 * i];
        s += (v.x + v.y) + (v.z + v.w);
    }
    #pragma unroll
    for (int o = 16; o > 0; o >>= 1) s += __shfl_xor_sync(0xffffffffu, s, o);
    if ((t & 31) == 0) red[t >> 5] = s;
    __syncthreads();
    const float ws = red[0] + red[1] + red[2] + red[3];

    const int c = 4 * t;
    const size_t kc = ((size_t)b * KDIM + k) * CDIM + c;
    float4 p = *(const float4*)(g_part + kc);
    #pragma unroll
    for (int sp = 1; sp < 4; ++sp) {
        float4 q = *(const float4*)(g_part + (size_t)sp * BDIM * KDIM * CDIM + kc);
        p.x += q.x; p.y += q.y; p.z += q.z; p.w += q.w;
    }
    float4 cv = *(const float4*)(cw + k * CDIM + c);
    float4 o4;
    o4.x = p.x - ws * cv.x;
    o4.y = p.y - ws * cv.y;
    o4.z = p.z - ws * cv.z;
    o4.w = p.w - ws * cv.w;
    *(float4*)(out + kc) = o4;
}

// ============================================================================
extern "C" void kernel_launch(void* const* d_in, const int* in_sizes, int n_in,
                              void* d_out, int out_size)
{
    (void)in_sizes; (void)n_in; (void)out_size;
    const float* x     = (const float*)d_in[0];   // [32,512,64,64]
    const float* cw    = (const float*)d_in[1];   // [32,512]
    const float* scale = (const float*)d_in[2];   // [32]
    float* out = (float*)d_out;                   // [32,32,512]

    cudaFuncSetAttribute(enc_k1, cudaFuncAttributeMaxDynamicSharedMemorySize,
                         58368);
    cudaFuncSetAttribute(enc_k2m, cudaFuncAttributeMaxDynamicSharedMemorySize,
                         87040);

    enc_k1 <<<dim3(16, 32), 256, 58368>>>(x, cw, scale);
    enc_k2m<<<dim3(4, 4, 32), 256, 87040>>>(x);
    enc_red<<<dim3(32, 32), 128>>>(cw, out);
}